// round 15
// baseline (speedup 1.0000x reference)
#include <cuda_runtime.h>
#include <math.h>

#define NB   64
#define NPB  4096
#define NN   (NB*NPB)      // 262144 nodes
#define CC   128
#define EE   (32*NN)       // 8388608 edges
#define KSEL (NPB/2)       // 2048
#define PP   (NB*KSEL)     // 131072 selected
#define BMW  (NN/32)       // 8192 bitmap words (32 KB)

__device__ float    g_score[NN];
__device__ float    g_norm[NN];
__device__ int      g_sidx[PP];
__device__ short    g_mask16[NN];    // node -> rank j; read only where bitmap bit set
__device__ unsigned g_bitmap[BMW];   // selected-node validity bits

#define PADI(i) ((i) + ((i) >> 5))

// ---------------------------------------------------------------------------
// K1: score = x.p, warp handles 8 rows (MLP=8). Default loads keep x warm in
// L2 for the fused kernel's gathers. Zeroes validity bitmap.
// ---------------------------------------------------------------------------
__global__ __launch_bounds__(256) void k_score(const float* __restrict__ x,
                                               const float* __restrict__ p) {
    int warp = threadIdx.x >> 5, lane = threadIdx.x & 31;
    int row0 = blockIdx.x * 64 + warp * 8;
    float4 pv = __ldg(((const float4*)p) + lane);
    const float4* xr = (const float4*)x + (size_t)row0 * 32 + lane;
    float4 v0 = xr[0];    float4 v1 = xr[32];
    float4 v2 = xr[64];   float4 v3 = xr[96];
    float4 v4 = xr[128];  float4 v5 = xr[160];
    float4 v6 = xr[192];  float4 v7 = xr[224];
    float s0 = v0.x*pv.x + v0.y*pv.y + v0.z*pv.z + v0.w*pv.w;
    float s1 = v1.x*pv.x + v1.y*pv.y + v1.z*pv.z + v1.w*pv.w;
    float s2 = v2.x*pv.x + v2.y*pv.y + v2.z*pv.z + v2.w*pv.w;
    float s3 = v3.x*pv.x + v3.y*pv.y + v3.z*pv.z + v3.w*pv.w;
    float s4 = v4.x*pv.x + v4.y*pv.y + v4.z*pv.z + v4.w*pv.w;
    float s5 = v5.x*pv.x + v5.y*pv.y + v5.z*pv.z + v5.w*pv.w;
    float s6 = v6.x*pv.x + v6.y*pv.y + v6.z*pv.z + v6.w*pv.w;
    float s7 = v7.x*pv.x + v7.y*pv.y + v7.z*pv.z + v7.w*pv.w;
    #pragma unroll
    for (int o = 16; o; o >>= 1) {
        s0 += __shfl_xor_sync(0xffffffffu, s0, o);
        s1 += __shfl_xor_sync(0xffffffffu, s1, o);
        s2 += __shfl_xor_sync(0xffffffffu, s2, o);
        s3 += __shfl_xor_sync(0xffffffffu, s3, o);
        s4 += __shfl_xor_sync(0xffffffffu, s4, o);
        s5 += __shfl_xor_sync(0xffffffffu, s5, o);
        s6 += __shfl_xor_sync(0xffffffffu, s6, o);
        s7 += __shfl_xor_sync(0xffffffffu, s7, o);
    }
    if (lane == 0) {
        float4* dst = (float4*)&g_score[row0];
        dst[0] = make_float4(s0, s1, s2, s3);
        dst[1] = make_float4(s4, s5, s6, s7);
    }
    int mi = blockIdx.x * 256 + threadIdx.x;
    if (mi < BMW) g_bitmap[mi] = 0u;
}

// ---------------------------------------------------------------------------
// K2: per-segment softmax + stable ascending bitonic argsort (block/batch).
// Emits first-k indices, scatters rank into int16 mask and validity bitmap
// for output block bo = NB-1-b (reference's batch-axis reversal).
// ---------------------------------------------------------------------------
__global__ __launch_bounds__(1024) void k_sort() {
    __shared__ float es[NPB];
    __shared__ unsigned long long keys[NPB + (NPB >> 5)];
    __shared__ float red[33];
    int b = blockIdx.x, tid = threadIdx.x;
    int lane = tid & 31, warp = tid >> 5;
    const int base = b * NPB;

    float m = -3.4e38f;
    for (int i = tid; i < NPB; i += 1024) {
        float v = g_score[base + i];
        es[i] = v;
        m = fmaxf(m, v);
    }
    #pragma unroll
    for (int o = 16; o; o >>= 1) m = fmaxf(m, __shfl_xor_sync(0xffffffffu, m, o));
    if (lane == 0) red[warp] = m;
    __syncthreads();
    if (warp == 0) {
        float v = red[lane];
        #pragma unroll
        for (int o = 16; o; o >>= 1) v = fmaxf(v, __shfl_xor_sync(0xffffffffu, v, o));
        if (lane == 0) red[32] = v;
    }
    __syncthreads();
    float M = red[32];

    float sum = 0.f;
    for (int i = tid; i < NPB; i += 1024) {
        float e = expf(es[i] - M);
        es[i] = e;
        sum += e;
    }
    __syncthreads();
    #pragma unroll
    for (int o = 16; o; o >>= 1) sum += __shfl_xor_sync(0xffffffffu, sum, o);
    if (lane == 0) red[warp] = sum;
    __syncthreads();
    if (warp == 0) {
        float v = red[lane];
        #pragma unroll
        for (int o = 16; o; o >>= 1) v += __shfl_xor_sync(0xffffffffu, v, o);
        if (lane == 0) red[32] = v;
    }
    __syncthreads();
    float S = red[32];

    for (int i = tid; i < NPB; i += 1024) {
        float ns = es[i] / S;
        g_norm[base + i] = ns;
        keys[PADI(i)] = ((unsigned long long)__float_as_uint(ns) << 32) | (unsigned)i;
    }
    __syncthreads();

    // sizes 2..32 in registers
    #pragma unroll
    for (int gg = 0; gg < 4; ++gg) {
        int idx = (warp * 4 + gg) * 32 + lane;
        unsigned long long k = keys[PADI(idx)];
        #pragma unroll
        for (int size = 2; size <= 32; size <<= 1) {
            #pragma unroll
            for (int stride = size >> 1; stride; stride >>= 1) {
                unsigned long long o = __shfl_xor_sync(0xffffffffu, k, stride);
                bool up    = ((idx & size) == 0);
                bool lower = ((lane & stride) == 0);
                k = (lower == up) ? (k < o ? k : o) : (k > o ? k : o);
            }
        }
        keys[PADI(idx)] = k;
    }

    for (int size = 64; size <= NPB; size <<= 1) {
        for (int stride = size >> 1; stride >= 32; stride >>= 1) {
            __syncthreads();
            for (int t = tid; t < NPB / 2; t += 1024) {
                int i = ((t & ~(stride - 1)) << 1) | (t & (stride - 1));
                int j = i + stride;
                unsigned long long a = keys[PADI(i)], cc2 = keys[PADI(j)];
                bool up = ((i & size) == 0);
                if ((a > cc2) == up) { keys[PADI(i)] = cc2; keys[PADI(j)] = a; }
            }
        }
        __syncthreads();
        #pragma unroll
        for (int gg = 0; gg < 4; ++gg) {
            int idx = (warp * 4 + gg) * 32 + lane;
            unsigned long long k = keys[PADI(idx)];
            bool up = ((idx & size) == 0);
            #pragma unroll
            for (int stride = 16; stride; stride >>= 1) {
                unsigned long long o = __shfl_xor_sync(0xffffffffu, k, stride);
                bool lower = ((lane & stride) == 0);
                k = (lower == up) ? (k < o ? k : o) : (k > o ? k : o);
            }
            keys[PADI(idx)] = k;
        }
    }
    __syncthreads();

    int bo = NB - 1 - b;
    for (int j = tid; j < KSEL; j += 1024) {
        int local = (int)(keys[PADI(j)] & 0xffffffffu);
        int g = (bo << 12) + local;
        g_sidx[b * KSEL + j] = local;
        g_mask16[g] = (short)j;                       // cluster = (bo<<11)+j
        atomicOr(&g_bitmap[g >> 5], 1u << (g & 31));  // validity bit
    }
}

// ---------------------------------------------------------------------------
// K3: persistent warp-fused kernel. 512-thread blocks, 3 per SM (reg-capped)
// -> 48 resident warps/SM. Warps 0-7 grid-stride over edge tiles, warps 8-15
// over selected rows. Bitmap in SMEM; rank gathers only for both-valid edges.
// ---------------------------------------------------------------------------
#define GFB  444                 // 3 blocks per SM
#define NEW  (GFB * 8)           // 3552 warps per role
#define T4   (EE / 4)            // 2097152 int4 pairs

__global__ __launch_bounds__(512, 3) void k_fused(const float* __restrict__ x,
                                                  const int4* __restrict__ se,
                                                  const int4* __restrict__ re,
                                                  float* __restrict__ out) {
    __shared__ unsigned bm[BMW];         // 32 KB
    int tid  = threadIdx.x;
    int warp = tid >> 5, lane = tid & 31;
    int q    = blockIdx.x;

    {
        uint4* d = (uint4*)bm;
        const uint4* s = (const uint4*)g_bitmap;
        d[tid]        = s[tid];
        d[tid + 512]  = s[tid + 512];
        d[tid + 1024] = s[tid + 1024];
        d[tid + 1536] = s[tid + 1536];
    }
    __syncthreads();

    if (warp < 8) {
        // ---- edge role: 64 int4-pairs per warp-iter (2/lane, MLP=4) ----
        int we = q * 8 + warp;
        float* os  = out + (size_t)PP * CC;
        float* orr = os + EE;
        #define DOEDGE(ns, nr, fsv, frv)                                        \
        {                                                                       \
            bool vs = (bm[(unsigned)(ns) >> 5] >> ((ns) & 31)) & 1u;            \
            bool vr = (bm[(unsigned)(nr) >> 5] >> ((nr) & 31)) & 1u;            \
            if (vs && vr) {                                                     \
                int a = __ldg(&g_mask16[ns]);                                   \
                int c = __ldg(&g_mask16[nr]);                                   \
                fsv = (float)((((ns) & ~4095) >> 1) + a);                       \
                frv = (float)((((nr) & ~4095) >> 1) + c);                       \
            } else { fsv = -1.0f; frv = -1.0f; }                                \
        }
        for (int s0 = we * 64; s0 < T4; s0 += NEW * 64) {
            int t = s0 + lane;
            int4 sv0 = __ldcs(se + t);        int4 rv0 = __ldcs(re + t);
            int4 sv1 = __ldcs(se + t + 32);   int4 rv1 = __ldcs(re + t + 32);
            #define DOQUAD(sv, rv, tt)                                          \
            {                                                                   \
                float4 fs, fr;                                                  \
                DOEDGE(sv.x, rv.x, fs.x, fr.x)                                  \
                DOEDGE(sv.y, rv.y, fs.y, fr.y)                                  \
                DOEDGE(sv.z, rv.z, fs.z, fr.z)                                  \
                DOEDGE(sv.w, rv.w, fs.w, fr.w)                                  \
                __stcs(((float4*)os)  + (tt), fs);                              \
                __stcs(((float4*)orr) + (tt), fr);                              \
            }
            DOQUAD(sv0, rv0, t)
            DOQUAD(sv1, rv1, t + 32)
            #undef DOQUAD
        }
        #undef DOEDGE
    } else {
        // ---- select role: 4 rows per warp-iter (MLP=4) ----
        int ws = q * 8 + (warp - 8);
        const float4* xb = (const float4*)x;
        float4* ob = (float4*)out;
        for (int i0 = ws * 4; i0 < PP; i0 += NEW * 4) {
            int b  = i0 >> 11;                 // 4-row tile never crosses a batch
            int jb = i0 & (KSEL - 1);
            const int* sp = &g_sidx[((NB - 1 - b) << 11) + jb];
            int l0 = __ldg(sp + 0), l1 = __ldg(sp + 1);
            int l2 = __ldg(sp + 2), l3 = __ldg(sp + 3);
            int g0 = (b << 12) + l0, g1 = (b << 12) + l1;
            int g2 = (b << 12) + l2, g3 = (b << 12) + l3;
            float c0 = __ldg(&g_norm[g0]), c1 = __ldg(&g_norm[g1]);
            float c2 = __ldg(&g_norm[g2]), c3 = __ldg(&g_norm[g3]);
            float4 a0 = xb[(size_t)g0 * 32 + lane];   // default: L2 reuse
            float4 a1 = xb[(size_t)g1 * 32 + lane];
            float4 a2 = xb[(size_t)g2 * 32 + lane];
            float4 a3 = xb[(size_t)g3 * 32 + lane];
            a0.x *= c0; a0.y *= c0; a0.z *= c0; a0.w *= c0;
            a1.x *= c1; a1.y *= c1; a1.z *= c1; a1.w *= c1;
            a2.x *= c2; a2.y *= c2; a2.z *= c2; a2.w *= c2;
            a3.x *= c3; a3.y *= c3; a3.z *= c3; a3.w *= c3;
            __stcs(ob + (size_t)(i0 + 0) * 32 + lane, a0);
            __stcs(ob + (size_t)(i0 + 1) * 32 + lane, a1);
            __stcs(ob + (size_t)(i0 + 2) * 32 + lane, a2);
            __stcs(ob + (size_t)(i0 + 3) * 32 + lane, a3);
            if (lane < 4) {
                int ii = i0 + lane;
                int gg = (b << 12) + ((lane == 0) ? l0 : (lane == 1) ? l1
                                     : (lane == 2) ? l2 : l3);
                out[(size_t)PP * CC + 2 * (size_t)EE + ii] =
                    (float)(gg < PP ? gg : PP - 1);
            }
        }
    }
}

// ---------------------------------------------------------------------------
extern "C" void kernel_launch(void* const* d_in, const int* in_sizes, int n_in,
                              void* d_out, int out_size) {
    const float* x         = (const float*)d_in[0];
    const float* p         = (const float*)d_in[1];
    const int*   senders   = (const int*)d_in[2];
    const int*   receivers = (const int*)d_in[3];
    float* out = (float*)d_out;

    k_score<<<NN / 64, 256>>>(x, p);
    k_sort <<<NB, 1024>>>();
    k_fused<<<GFB, 512>>>(x, (const int4*)senders, (const int4*)receivers, out);
}